// round 2
// baseline (speedup 1.0000x reference)
#include <cuda_runtime.h>
#include <cstdint>

#define TPB   128
#define TILE  128
#define NBLK_MAX 740            // 148 SMs * 5 blocks (40 KB smem each)

#define IN_FLOATS  (TILE * 26)  // A(9)+B(9)+u(3)+v(3)+a(1)+b(1) per pair
#define OUT_FLOATS (TILE * 13)  // z2(9)+z1(3)+z0(1) per pair
#define IN_BYTES   (IN_FLOATS * 4)

__device__ __forceinline__ uint32_t s2u(const void* p) {
    return (uint32_t)__cvta_generic_to_shared(p);
}
__device__ __forceinline__ void bulk_g2s(uint32_t dst, const void* src, int bytes, uint32_t mb) {
    asm volatile(
        "cp.async.bulk.shared::cta.global.mbarrier::complete_tx::bytes [%0], [%1], %2, [%3];"
        :: "r"(dst), "l"(src), "r"(bytes), "r"(mb) : "memory");
}
__device__ __forceinline__ void bulk_s2g(void* dst, uint32_t src, int bytes) {
    asm volatile(
        "cp.async.bulk.global.shared::cta.bulk_group [%0], [%1], %2;"
        :: "l"(dst), "r"(src), "r"(bytes) : "memory");
}
__device__ __forceinline__ void mbar_init(uint32_t mb, int cnt) {
    asm volatile("mbarrier.init.shared.b64 [%0], %1;" :: "r"(mb), "r"(cnt) : "memory");
}
__device__ __forceinline__ void mbar_expect_tx(uint32_t mb, int bytes) {
    asm volatile("mbarrier.arrive.expect_tx.shared.b64 _, [%0], %1;"
                 :: "r"(mb), "r"(bytes) : "memory");
}
__device__ __forceinline__ void mbar_wait(uint32_t mb, int parity) {
    asm volatile(
        "{\n\t.reg .pred P;\n\t"
        "WL_%=:\n\t"
        "mbarrier.try_wait.parity.shared.b64 P, [%0], %1, 0x989680;\n\t"
        "@P bra.uni WD_%=;\n\t"
        "bra.uni WL_%=;\n\t"
        "WD_%=:\n\t}"
        :: "r"(mb), "r"(parity) : "memory");
}

// ---- shared compute: the 7 coupled contractions, fully inlined ----
__device__ __forceinline__ void tp_compute(
    float a, float b, const float* u, const float* v,
    const float* A, const float* B,
    float& z0, float* z1, float* z2)
{
    z0 = a * b;
    #pragma unroll
    for (int i = 0; i < 3; i++) z0 = fmaf(u[i], v[i], z0);
    #pragma unroll
    for (int i = 0; i < 9; i++) z0 = fmaf(A[i], B[i], z0);

    #pragma unroll
    for (int i = 0; i < 3; i++) {
        float s = fmaf(a, v[i], b * u[i]);
        #pragma unroll
        for (int d = 0; d < 3; d++) {
            s = fmaf(u[d], B[d * 3 + i], s);       // u . B
            s = fmaf(A[i * 3 + d], v[d], s);       // A . v
        }
        z1[i] = s;
    }
    #pragma unroll
    for (int i = 0; i < 3; i++)
        #pragma unroll
        for (int j = 0; j < 3; j++) {
            float s = fmaf(a, B[i * 3 + j], b * A[i * 3 + j]);
            s = fmaf(u[i], v[j], s);
            #pragma unroll
            for (int k = 0; k < 3; k++)
                s = fmaf(A[i * 3 + k], B[k * 3 + j], s);   // A @ B
            z2[i * 3 + j] = s;
        }
}

// ---- persistent double-buffered TMA pipeline ----
__global__ __launch_bounds__(TPB) void tp_tma(
    const float* __restrict__ x0, const float* __restrict__ y0,
    const float* __restrict__ x1, const float* __restrict__ y1,
    const float* __restrict__ x2, const float* __restrict__ y2,
    float* __restrict__ out, long long NC)
{
    __shared__ __align__(16) float sIn[2][IN_FLOATS];
    __shared__ __align__(16) float sOut[2][OUT_FLOATS];
    __shared__ __align__(8) unsigned long long mbar[2];

    const int t = threadIdx.x;
    const long long ntiles = NC / TILE;
    const long long rem = NC - ntiles * TILE;
    float* o0 = out;
    float* o1 = out + NC;
    float* o2 = out + 4 * NC;

    if (t == 0) {
        mbar_init(s2u(&mbar[0]), 1);
        mbar_init(s2u(&mbar[1]), 1);
        asm volatile("fence.proxy.async.shared::cta;" ::: "memory");
    }
    __syncthreads();

    auto issue = [&](int s, long long tile) {
        uint32_t mb = s2u(&mbar[s]);
        mbar_expect_tx(mb, IN_BYTES);
        bulk_g2s(s2u(&sIn[s][0]),         x2 + tile * (TILE * 9), TILE * 36, mb);
        bulk_g2s(s2u(&sIn[s][TILE * 9]),  y2 + tile * (TILE * 9), TILE * 36, mb);
        bulk_g2s(s2u(&sIn[s][TILE * 18]), x1 + tile * (TILE * 3), TILE * 12, mb);
        bulk_g2s(s2u(&sIn[s][TILE * 21]), y1 + tile * (TILE * 3), TILE * 12, mb);
        bulk_g2s(s2u(&sIn[s][TILE * 24]), x0 + tile * TILE,       TILE * 4,  mb);
        bulk_g2s(s2u(&sIn[s][TILE * 25]), y0 + tile * TILE,       TILE * 4,  mb);
    };

    long long myN = 0;
    if ((long long)blockIdx.x < ntiles)
        myN = (ntiles - 1 - blockIdx.x) / gridDim.x + 1;

    if (t == 0 && myN > 0) {
        issue(0, blockIdx.x);
        if (myN > 1) issue(1, blockIdx.x + (long long)gridDim.x);
    }

    for (long long k = 0; k < myN; k++) {
        const int s = (int)(k & 1);
        const long long tile = blockIdx.x + k * (long long)gridDim.x;

        mbar_wait(s2u(&mbar[s]), (int)((k >> 1) & 1));

        // operands (stride 9 / 3 / 1 in smem words — all conflict-free)
        const float* in = sIn[s];
        float A[9], B[9], u[3], v[3];
        float a = in[TILE * 24 + t], b = in[TILE * 25 + t];
        #pragma unroll
        for (int i = 0; i < 9; i++) { A[i] = in[t * 9 + i]; B[i] = in[TILE * 9 + t * 9 + i]; }
        #pragma unroll
        for (int i = 0; i < 3; i++) { u[i] = in[TILE * 18 + t * 3 + i]; v[i] = in[TILE * 21 + t * 3 + i]; }

        float z0, z1[3], z2[9];
        tp_compute(a, b, u, v, A, B, z0, z1, z2);

        // out-buffer s must be done being read by the store from iteration k-2
        if (t == 0) asm volatile("cp.async.bulk.wait_group.read 1;" ::: "memory");
        __syncthreads();   // also guarantees sIn[s] fully consumed by all threads

        float* po = sOut[s];
        #pragma unroll
        for (int i = 0; i < 9; i++) po[t * 9 + i] = z2[i];
        #pragma unroll
        for (int i = 0; i < 3; i++) po[TILE * 9 + t * 3 + i] = z1[i];
        po[TILE * 12 + t] = z0;

        // refill this stage for tile k+2 while we finish the epilogue
        if (t == 0 && k + 2 < myN) issue(s, tile + 2LL * gridDim.x);
        __syncthreads();   // sOut[s] fully written

        if (t == 0) {
            asm volatile("fence.proxy.async.shared::cta;" ::: "memory");
            bulk_s2g(o2 + tile * (TILE * 9), s2u(&sOut[s][0]),         TILE * 36);
            bulk_s2g(o1 + tile * (TILE * 3), s2u(&sOut[s][TILE * 9]),  TILE * 12);
            bulk_s2g(o0 + tile * TILE,       s2u(&sOut[s][TILE * 12]), TILE * 4);
            asm volatile("cp.async.bulk.commit_group;" ::: "memory");
        }
    }

    if (t == 0) asm volatile("cp.async.bulk.wait_group 0;" ::: "memory");
    __syncthreads();

    // tail pairs (NC % TILE) handled by block 0 with direct accesses
    if (blockIdx.x == 0 && rem > 0 && t < (int)rem) {
        long long p = ntiles * TILE + t;
        float a = x0[p], b = y0[p];
        float u[3], v[3], A[9], B[9];
        #pragma unroll
        for (int i = 0; i < 3; i++) { u[i] = x1[p * 3 + i]; v[i] = y1[p * 3 + i]; }
        #pragma unroll
        for (int i = 0; i < 9; i++) { A[i] = x2[p * 9 + i]; B[i] = y2[p * 9 + i]; }
        float z0, z1[3], z2[9];
        tp_compute(a, b, u, v, A, B, z0, z1, z2);
        o0[p] = z0;
        #pragma unroll
        for (int i = 0; i < 3; i++) o1[p * 3 + i] = z1[i];
        #pragma unroll
        for (int i = 0; i < 9; i++) o2[p * 9 + i] = z2[i];
    }
}

// ---- fallback: simple one-thread-per-pair kernel (any shape/alignment) ----
__global__ void tp_simple(
    const float* __restrict__ x0, const float* __restrict__ y0,
    const float* __restrict__ x1, const float* __restrict__ y1,
    const float* __restrict__ x2, const float* __restrict__ y2,
    float* __restrict__ out, long long NC)
{
    long long p = (long long)blockIdx.x * blockDim.x + threadIdx.x;
    if (p >= NC) return;
    float a = x0[p], b = y0[p];
    float u[3], v[3], A[9], B[9];
    #pragma unroll
    for (int i = 0; i < 3; i++) { u[i] = x1[p * 3 + i]; v[i] = y1[p * 3 + i]; }
    #pragma unroll
    for (int i = 0; i < 9; i++) { A[i] = x2[p * 9 + i]; B[i] = y2[p * 9 + i]; }
    float z0, z1[3], z2[9];
    tp_compute(a, b, u, v, A, B, z0, z1, z2);
    out[p] = z0;
    #pragma unroll
    for (int i = 0; i < 3; i++) out[NC + p * 3 + i] = z1[i];
    #pragma unroll
    for (int i = 0; i < 9; i++) out[4 * NC + p * 9 + i] = z2[i];
}

extern "C" void kernel_launch(void* const* d_in, const int* in_sizes, int n_in,
                              void* d_out, int out_size)
{
    const long long NC = (long long)out_size / 13;

    // Classify by element count; x precedes y within each size class in both
    // plausible metadata orderings.
    const float *x0 = nullptr, *y0 = nullptr, *x1 = nullptr, *y1 = nullptr,
                *x2 = nullptr, *y2 = nullptr;
    for (int i = 0; i < n_in; i++) {
        long long s = in_sizes[i];
        const float* p = (const float*)d_in[i];
        if (s == NC)          { if (!x0) x0 = p; else y0 = p; }
        else if (s == 3 * NC) { if (!x1) x1 = p; else y1 = p; }
        else if (s == 9 * NC) { if (!x2) x2 = p; else y2 = p; }
    }

    // TMA bulk path needs 16B-aligned global addresses everywhere.
    auto a16 = [](const void* p) { return (((uintptr_t)p) & 15) == 0; };
    bool ok = (NC % 4 == 0) && a16(x0) && a16(y0) && a16(x1) && a16(y1) &&
              a16(x2) && a16(y2) && a16(d_out);

    if (ok) {
        long long ntiles = NC / TILE;
        int nblk = (int)(ntiles < 1 ? 1 : (ntiles < NBLK_MAX ? ntiles : NBLK_MAX));
        tp_tma<<<nblk, TPB>>>(x0, y0, x1, y1, x2, y2, (float*)d_out, NC);
    } else {
        int nblk = (int)((NC + 255) / 256);
        tp_simple<<<nblk, 256>>>(x0, y0, x1, y1, x2, y2, (float*)d_out, NC);
    }
}